// round 2
// baseline (speedup 1.0000x reference)
#include <cuda_runtime.h>

// Problem constants (fixed by the dataset).
#define KB 4          // batch
#define KS 4096       // sequence
#define KH 16         // heads
#define KD 64         // head dim
#define KC 64         // our chunk size (math is chunk-invariant)
#define KN (KS / KC)          // 64 chunks per (b,h)
#define KBH (KB * KH)         // 64
#define KCHUNKS (KBH * KN)    // 4096 total chunks
#define KROW (KH * KD)        // 1024 floats between consecutive s
#define PITCH 68              // padded smem pitch (bank rotation, keeps 16B align)

// Scratch: per-chunk KV outer products, then overwritten in place with the
// exclusive prefix sums. 4096 chunks * 64*64 floats = 64 MiB.
__device__ float g_kv[(size_t)KCHUNKS * KD * KD];

// ---------------------------------------------------------------------------
// Kernel A: kv[g][d][e] = sum_j K[g][j][d] * V[g][j][e]   (64x64x64 per block)
// ---------------------------------------------------------------------------
__global__ __launch_bounds__(256) void kv_kernel(const float* __restrict__ K,
                                                 const float* __restrict__ V) {
    __shared__ float Ks[KC][KD];
    __shared__ float Vs[KC][KD];

    const int g = blockIdx.x;
    const int b = g >> 10;            // / (KH*KN)
    const int h = (g >> 6) & (KH - 1);
    const int n = g & (KN - 1);
    const int tid = threadIdx.x;
    const int base = ((b * KS + n * KC) * KH + h) * KD;

    // Load K and V chunks (64x64 each) with coalesced float4 loads.
#pragma unroll
    for (int t = tid; t < KC * KD / 4; t += 256) {
        const int row = t >> 4;
        const int col = (t & 15) << 2;
        const int ga = base + row * KROW + col;
        *(float4*)&Ks[row][col] = *(const float4*)&K[ga];
        *(float4*)&Vs[row][col] = *(const float4*)&V[ga];
    }
    __syncthreads();

    const int tx = tid & 15;          // e-group
    const int ty = tid >> 4;          // d-group
    const int d0 = ty << 2;
    const int e0 = tx << 2;

    float acc[4][4];
#pragma unroll
    for (int a = 0; a < 4; ++a)
#pragma unroll
        for (int e = 0; e < 4; ++e) acc[a][e] = 0.0f;

#pragma unroll 4
    for (int j = 0; j < KC; ++j) {
        const float4 kd = *(const float4*)&Ks[j][d0];
        const float4 ve = *(const float4*)&Vs[j][e0];
        const float kf[4] = {kd.x, kd.y, kd.z, kd.w};
        const float vf[4] = {ve.x, ve.y, ve.z, ve.w};
#pragma unroll
        for (int a = 0; a < 4; ++a)
#pragma unroll
            for (int e = 0; e < 4; ++e) acc[a][e] += kf[a] * vf[e];
    }

    float* outp = g_kv + (size_t)g * (KD * KD);
#pragma unroll
    for (int a = 0; a < 4; ++a) {
        *(float4*)&outp[(d0 + a) * KD + e0] =
            make_float4(acc[a][0], acc[a][1], acc[a][2], acc[a][3]);
    }
}

// ---------------------------------------------------------------------------
// Kernel B: in-place exclusive prefix sum of g_kv over the chunk axis.
// One thread per (d,e) entry; 1024 blocks * 256 threads = 64 bh * 4096 entries.
// ---------------------------------------------------------------------------
__global__ __launch_bounds__(256) void scan_kernel() {
    const int bh = blockIdx.x >> 4;
    const int entry = ((blockIdx.x & 15) << 8) + threadIdx.x;  // 0..4095
    size_t addr = (size_t)bh * KN * (KD * KD) + entry;

    float run = 0.0f;
#pragma unroll 8
    for (int n = 0; n < KN; ++n) {
        const float val = g_kv[addr];
        g_kv[addr] = run;
        run += val;
        addr += KD * KD;
    }
}

// ---------------------------------------------------------------------------
// Kernel C: per chunk,  O = tril(Q K^T) V  +  Q * KV_prev
// Smem operands transposed (Qt/Kt/St are k-major, pitch 68) so every inner
// LDS is a conflict-free float4 with warp broadcast.
// ---------------------------------------------------------------------------
__global__ __launch_bounds__(256) void out_kernel(const float* __restrict__ Q,
                                                  const float* __restrict__ K,
                                                  const float* __restrict__ V,
                                                  float* __restrict__ O) {
    extern __shared__ float sm[];
    float* Qt = sm;                       // [KD][PITCH]  Qt[d][i]
    float* Kt = Qt + KD * PITCH;          // [KD][PITCH]  Kt[d][j]
    float* St = Kt + KD * PITCH;          // [KC][PITCH]  St[j][i] (masked scores)
    float* Vs = St + KC * PITCH;          // [KC][KD]     row-major
    float* Ps = Vs + KC * KD;             // [KD][KD]     row-major (KV_prev)

    const int g = blockIdx.x;
    const int b = g >> 10;
    const int h = (g >> 6) & (KH - 1);
    const int n = g & (KN - 1);
    const int tid = threadIdx.x;
    const int base = ((b * KS + n * KC) * KH + h) * KD;
    const float* kvp = g_kv + (size_t)g * (KD * KD);

    // Load Q,K (transposed into smem), V (row-major), P = KV_prev (row-major).
#pragma unroll
    for (int t = tid; t < KC * KD / 4; t += 256) {
        const int row = t >> 4;           // i (for Q) / j (for K,V)
        const int col = (t & 15) << 2;    // d (or e)
        const int ga = base + row * KROW + col;
        const float4 qv = *(const float4*)&Q[ga];
        const float4 kv4 = *(const float4*)&K[ga];
        Qt[(col + 0) * PITCH + row] = qv.x;
        Qt[(col + 1) * PITCH + row] = qv.y;
        Qt[(col + 2) * PITCH + row] = qv.z;
        Qt[(col + 3) * PITCH + row] = qv.w;
        Kt[(col + 0) * PITCH + row] = kv4.x;
        Kt[(col + 1) * PITCH + row] = kv4.y;
        Kt[(col + 2) * PITCH + row] = kv4.z;
        Kt[(col + 3) * PITCH + row] = kv4.w;
        *(float4*)&Vs[row * KD + col] = *(const float4*)&V[ga];
    }
#pragma unroll
    for (int t = tid; t < KD * KD / 4; t += 256)
        *(float4*)&Ps[t << 2] = *(const float4*)&kvp[t << 2];
    __syncthreads();

    const int tx = tid & 15;
    const int ty = tid >> 4;
    const int i0 = ty << 2;               // output rows
    const int j0 = tx << 2;               // score cols / output cols (e)

    // --- Stage 1: scores S[i][j] = sum_d Q[i][d] * K[j][d] ---
    float acc[4][4];
#pragma unroll
    for (int a = 0; a < 4; ++a)
#pragma unroll
        for (int e = 0; e < 4; ++e) acc[a][e] = 0.0f;

#pragma unroll 4
    for (int d = 0; d < KD; ++d) {
        const float4 qa = *(const float4*)&Qt[d * PITCH + i0];
        const float4 kb = *(const float4*)&Kt[d * PITCH + j0];
        const float qf[4] = {qa.x, qa.y, qa.z, qa.w};
        const float kf[4] = {kb.x, kb.y, kb.z, kb.w};
#pragma unroll
        for (int a = 0; a < 4; ++a)
#pragma unroll
            for (int e = 0; e < 4; ++e) acc[a][e] += qf[a] * kf[e];
    }

    // Masked transposed store: St[j][i] = (j <= i) ? S[i][j] : 0
#pragma unroll
    for (int jj = 0; jj < 4; ++jj) {
        const int j = j0 + jj;
        float4 r;
        r.x = (j <= i0 + 0) ? acc[0][jj] : 0.0f;
        r.y = (j <= i0 + 1) ? acc[1][jj] : 0.0f;
        r.z = (j <= i0 + 2) ? acc[2][jj] : 0.0f;
        r.w = (j <= i0 + 3) ? acc[3][jj] : 0.0f;
        *(float4*)&St[j * PITCH + i0] = r;
    }
    __syncthreads();

    // --- Stage 2: O[i][e] = sum_j St[j][i]*V[j][e] + sum_d Qt[d][i]*P[d][e] ---
    float o[4][4];
#pragma unroll
    for (int a = 0; a < 4; ++a)
#pragma unroll
        for (int e = 0; e < 4; ++e) o[a][e] = 0.0f;

#pragma unroll 4
    for (int j = 0; j < KC; ++j) {
        const float4 sa = *(const float4*)&St[j * PITCH + i0];
        const float4 vb = *(const float4*)&Vs[j * KD + j0];
        const float sf[4] = {sa.x, sa.y, sa.z, sa.w};
        const float vf[4] = {vb.x, vb.y, vb.z, vb.w};
#pragma unroll
        for (int a = 0; a < 4; ++a)
#pragma unroll
            for (int e = 0; e < 4; ++e) o[a][e] += sf[a] * vf[e];
    }
#pragma unroll 4
    for (int d = 0; d < KD; ++d) {
        const float4 qa = *(const float4*)&Qt[d * PITCH + i0];
        const float4 pb = *(const float4*)&Ps[d * KD + j0];
        const float qf[4] = {qa.x, qa.y, qa.z, qa.w};
        const float pf[4] = {pb.x, pb.y, pb.z, pb.w};
#pragma unroll
        for (int a = 0; a < 4; ++a)
#pragma unroll
            for (int e = 0; e < 4; ++e) o[a][e] += qf[a] * pf[e];
    }

    // Store output (coalesced float4 per row).
#pragma unroll
    for (int a = 0; a < 4; ++a) {
        const int ga = base + (i0 + a) * KROW + j0;
        *(float4*)&O[ga] = make_float4(o[a][0], o[a][1], o[a][2], o[a][3]);
    }
}

// ---------------------------------------------------------------------------
// Launch
// ---------------------------------------------------------------------------
static const int kOutSmem =
    (2 * KD * PITCH + KC * PITCH + KC * KD + KD * KD) * (int)sizeof(float);  // 84992 B

extern "C" void kernel_launch(void* const* d_in, const int* in_sizes, int n_in,
                              void* d_out, int out_size) {
    const float* q = (const float*)d_in[0];
    const float* k = (const float*)d_in[1];
    const float* v = (const float*)d_in[2];
    // d_in[3] = attn_mask: unused by the reference forward.
    float* out = (float*)d_out;

    cudaFuncSetAttribute(out_kernel, cudaFuncAttributeMaxDynamicSharedMemorySize,
                         kOutSmem);

    kv_kernel<<<KCHUNKS, 256>>>(k, v);
    scan_kernel<<<KBH * 16, 256>>>();
    out_kernel<<<KCHUNKS, 256, kOutSmem>>>(q, k, v, out);
}

// round 4
// speedup vs baseline: 1.6379x; 1.6379x over previous
#include <cuda_runtime.h>
#include <cstdint>

// Problem constants.
#define KB 4
#define KS 4096
#define KH 16
#define KD 64
#define KC 128                 // chunk size (math is chunk-invariant)
#define KN (KS / KC)           // 32 chunks per (b,h)
#define KBH (KB * KH)          // 64
#define KCHUNKS (KBH * KN)     // 2048
#define KROW (KH * KD)         // 1024 floats between consecutive s

// Smem pitches (banks: chosen so fragment lane-addressing is conflict-free)
#define PQ 68     // [row][d] operands read with lane>>2 on the row axis (68%32==4)
#define PV 72     // [k][n] operands read with lane&3 on the row axis  (72%32==8)
#define PS 132    // S matrix [i][j], j range 128 (132%32==4)
#define PKT 132   // K^T in kv kernel [d][j], j range 128

// Scratch: per-chunk KV outer products -> exclusive prefix states. 32 MiB.
__device__ float g_kv[(size_t)KCHUNKS * KD * KD];

__device__ __forceinline__ unsigned f2tf(float x) {
    unsigned u;
    asm("cvt.rna.tf32.f32 %0, %1;" : "=r"(u) : "f"(x));
    return u;
}

__device__ __forceinline__ void mma_tf32(float* c, const unsigned* a, const unsigned* b) {
    asm volatile(
        "mma.sync.aligned.m16n8k8.row.col.f32.tf32.tf32.f32 "
        "{%0,%1,%2,%3}, {%4,%5,%6,%7}, {%8,%9}, {%0,%1,%2,%3};"
        : "+f"(c[0]), "+f"(c[1]), "+f"(c[2]), "+f"(c[3])
        : "r"(a[0]), "r"(a[1]), "r"(a[2]), "r"(a[3]), "r"(b[0]), "r"(b[1]));
}

// ---------------------------------------------------------------------------
// Kernel A: KV[d][e] = sum_j K[j][d] * V[j][e], per chunk. 64x64x128 per block.
// Block 128 (4 warps, 2x2 tile of 32x32 warp tiles).
// ---------------------------------------------------------------------------
__global__ __launch_bounds__(128) void kv_kernel(const float* __restrict__ K,
                                                 const float* __restrict__ V) {
    extern __shared__ unsigned sm_u[];
    unsigned* Kt = sm_u;                  // [KD][PKT]  Kt[d][j], tf32 bits
    unsigned* Vs = sm_u + KD * PKT;       // [KC][PV]   Vs[j][e], tf32 bits

    const int g = blockIdx.x;
    const int b = g >> 9;                 // / (KH*KN) = /512
    const int h = (g >> 5) & (KH - 1);
    const int n = g & (KN - 1);
    const int tid = threadIdx.x;
    const int base = ((b * KS + n * KC) * KH + h) * KD;

    // Load K (transposed) and V chunks, converting to tf32.
#pragma unroll
    for (int t = tid; t < KC * KD / 4; t += 128) {
        const int row = t >> 4;           // j
        const int col = (t & 15) << 2;    // d / e
        const int ga = base + row * KROW + col;
        const float4 kq = *(const float4*)&K[ga];
        Kt[(col + 0) * PKT + row] = f2tf(kq.x);
        Kt[(col + 1) * PKT + row] = f2tf(kq.y);
        Kt[(col + 2) * PKT + row] = f2tf(kq.z);
        Kt[(col + 3) * PKT + row] = f2tf(kq.w);
        const float4 vq = *(const float4*)&V[ga];
        uint4 vu = make_uint4(f2tf(vq.x), f2tf(vq.y), f2tf(vq.z), f2tf(vq.w));
        *(uint4*)&Vs[row * PV + col] = vu;
    }
    __syncthreads();

    const int wid = tid >> 5;
    const int lane = tid & 31;
    const int grp = lane >> 2;            // 0..7
    const int tg = lane & 3;              // 0..3
    const int wm = (wid >> 1) << 5;       // warp d-origin: 0 or 32
    const int wn = (wid & 1) << 5;        // warp e-origin: 0 or 32

    float acc[2][4][4];
#pragma unroll
    for (int mi = 0; mi < 2; ++mi)
#pragma unroll
        for (int ni = 0; ni < 4; ++ni)
#pragma unroll
            for (int r = 0; r < 4; ++r) acc[mi][ni][r] = 0.0f;

#pragma unroll
    for (int j0 = 0; j0 < KC; j0 += 8) {
        unsigned a[2][4], bb[4][2];
#pragma unroll
        for (int mi = 0; mi < 2; ++mi) {
            const int d = wm + (mi << 4);
            a[mi][0] = Kt[(d + grp) * PKT + j0 + tg];
            a[mi][1] = Kt[(d + grp + 8) * PKT + j0 + tg];
            a[mi][2] = Kt[(d + grp) * PKT + j0 + tg + 4];
            a[mi][3] = Kt[(d + grp + 8) * PKT + j0 + tg + 4];
        }
#pragma unroll
        for (int ni = 0; ni < 4; ++ni) {
            const int e = wn + (ni << 3) + grp;
            bb[ni][0] = Vs[(j0 + tg) * PV + e];
            bb[ni][1] = Vs[(j0 + tg + 4) * PV + e];
        }
#pragma unroll
        for (int mi = 0; mi < 2; ++mi)
#pragma unroll
            for (int ni = 0; ni < 4; ++ni) mma_tf32(acc[mi][ni], a[mi], bb[ni]);
    }

    float* outp = g_kv + (size_t)g * (KD * KD);
#pragma unroll
    for (int mi = 0; mi < 2; ++mi)
#pragma unroll
        for (int ni = 0; ni < 4; ++ni) {
            const int d = wm + (mi << 4) + grp;
            const int e = wn + (ni << 3) + (tg << 1);
            *(float2*)&outp[d * KD + e] = make_float2(acc[mi][ni][0], acc[mi][ni][1]);
            *(float2*)&outp[(d + 8) * KD + e] = make_float2(acc[mi][ni][2], acc[mi][ni][3]);
        }
}

// ---------------------------------------------------------------------------
// Kernel B: in-place exclusive prefix over chunks. fp32.
// ---------------------------------------------------------------------------
__global__ __launch_bounds__(256) void scan_kernel() {
    const int bh = blockIdx.x >> 4;
    const int entry = ((blockIdx.x & 15) << 8) + threadIdx.x;  // 0..4095
    size_t addr = (size_t)bh * KN * (KD * KD) + entry;

    float run = 0.0f;
#pragma unroll 8
    for (int n = 0; n < KN; ++n) {
        const float val = g_kv[addr];
        g_kv[addr] = run;
        run += val;
        addr += KD * KD;
    }
}

// ---------------------------------------------------------------------------
// Kernel C: O = tril(Q K^T) V + Q * KV_prev, per 128-chunk.
// Block 256 (8 warps). Stage1 S=QK^T (warp tile 32x64), mask, store tf32 to Ss.
// Stage2 O = Ss*V + Q*P (warp tile 32x32).
// ---------------------------------------------------------------------------
__global__ __launch_bounds__(256) void out_kernel(const float* __restrict__ Q,
                                                  const float* __restrict__ K,
                                                  const float* __restrict__ V,
                                                  float* __restrict__ O) {
    extern __shared__ unsigned sm_u[];
    unsigned* Qs = sm_u;                          // [KC][PQ]  Q[i][d]
    unsigned* Ks = Qs + KC * PQ;                  // [KC][PQ]  K[j][d]
    unsigned* Vs = Ks + KC * PQ;                  // [KC][PV]  V[j][e]
    unsigned* Ps = Vs + KC * PV;                  // [KD][PV]  P[d][e]
    unsigned* Ss = Ps + KD * PV;                  // [KC][PS]  S[i][j] masked, tf32

    const int g = blockIdx.x;
    const int b = g >> 9;
    const int h = (g >> 5) & (KH - 1);
    const int n = g & (KN - 1);
    const int tid = threadIdx.x;
    const int base = ((b * KS + n * KC) * KH + h) * KD;
    const float* kvp = g_kv + (size_t)g * (KD * KD);

    // Loads (convert to tf32).
#pragma unroll
    for (int t = tid; t < KC * KD / 4; t += 256) {
        const int row = t >> 4;
        const int col = (t & 15) << 2;
        const int ga = base + row * KROW + col;
        const float4 qq = *(const float4*)&Q[ga];
        *(uint4*)&Qs[row * PQ + col] =
            make_uint4(f2tf(qq.x), f2tf(qq.y), f2tf(qq.z), f2tf(qq.w));
        const float4 kk = *(const float4*)&K[ga];
        *(uint4*)&Ks[row * PQ + col] =
            make_uint4(f2tf(kk.x), f2tf(kk.y), f2tf(kk.z), f2tf(kk.w));
        const float4 vv = *(const float4*)&V[ga];
        *(uint4*)&Vs[row * PV + col] =
            make_uint4(f2tf(vv.x), f2tf(vv.y), f2tf(vv.z), f2tf(vv.w));
    }
#pragma unroll
    for (int t = tid; t < KD * KD / 4; t += 256) {
        const int d = t >> 4;
        const int e = (t & 15) << 2;
        const float4 pp = *(const float4*)&kvp[d * KD + e];
        *(uint4*)&Ps[d * PV + e] =
            make_uint4(f2tf(pp.x), f2tf(pp.y), f2tf(pp.z), f2tf(pp.w));
    }
    __syncthreads();

    const int wid = tid >> 5;
    const int lane = tid & 31;
    const int grp = lane >> 2;
    const int tg = lane & 3;

    // ---- Stage 1: S = Q K^T (128x128x64), warp tile 32x64 (warps 4x2) ----
    {
        const int wm = (wid >> 1) << 5;    // i-origin
        const int wn = (wid & 1) << 6;     // j-origin

        float acc[2][8][4];
#pragma unroll
        for (int mi = 0; mi < 2; ++mi)
#pragma unroll
            for (int ni = 0; ni < 8; ++ni)
#pragma unroll
                for (int r = 0; r < 4; ++r) acc[mi][ni][r] = 0.0f;

#pragma unroll
        for (int d0 = 0; d0 < KD; d0 += 8) {
            unsigned a[2][4], bb[8][2];
#pragma unroll
            for (int mi = 0; mi < 2; ++mi) {
                const int i = wm + (mi << 4);
                a[mi][0] = Qs[(i + grp) * PQ + d0 + tg];
                a[mi][1] = Qs[(i + grp + 8) * PQ + d0 + tg];
                a[mi][2] = Qs[(i + grp) * PQ + d0 + tg + 4];
                a[mi][3] = Qs[(i + grp + 8) * PQ + d0 + tg + 4];
            }
#pragma unroll
            for (int ni = 0; ni < 8; ++ni) {
                const int j = wn + (ni << 3) + grp;
                bb[ni][0] = Ks[j * PQ + d0 + tg];
                bb[ni][1] = Ks[j * PQ + d0 + tg + 4];
            }
#pragma unroll
            for (int mi = 0; mi < 2; ++mi)
#pragma unroll
                for (int ni = 0; ni < 8; ++ni) mma_tf32(acc[mi][ni], a[mi], bb[ni]);
        }

        // Mask (j<=i) and store tf32 to Ss[i][j].
#pragma unroll
        for (int mi = 0; mi < 2; ++mi)
#pragma unroll
            for (int ni = 0; ni < 8; ++ni) {
                const int i0r = wm + (mi << 4) + grp;
                const int jc = wn + (ni << 3) + (tg << 1);
                Ss[i0r * PS + jc]     = (jc     <= i0r) ? f2tf(acc[mi][ni][0]) : 0u;
                Ss[i0r * PS + jc + 1] = (jc + 1 <= i0r) ? f2tf(acc[mi][ni][1]) : 0u;
                Ss[(i0r + 8) * PS + jc]     = (jc     <= i0r + 8) ? f2tf(acc[mi][ni][2]) : 0u;
                Ss[(i0r + 8) * PS + jc + 1] = (jc + 1 <= i0r + 8) ? f2tf(acc[mi][ni][3]) : 0u;
            }
    }
    __syncthreads();

    // ---- Stage 2: O = Ss*V + Q*P, warp tile 32x32 (warps 4x2) ----
    {
        const int wm = (wid >> 1) << 5;    // i-origin
        const int wn = (wid & 1) << 5;     // e-origin

        float acc[2][4][4];
#pragma unroll
        for (int mi = 0; mi < 2; ++mi)
#pragma unroll
            for (int ni = 0; ni < 4; ++ni)
#pragma unroll
                for (int r = 0; r < 4; ++r) acc[mi][ni][r] = 0.0f;

        // 2a: sum over j (128)
#pragma unroll
        for (int j0 = 0; j0 < KC; j0 += 8) {
            unsigned a[2][4], bb[4][2];
#pragma unroll
            for (int mi = 0; mi < 2; ++mi) {
                const int i = wm + (mi << 4);
                a[mi][0] = Ss[(i + grp) * PS + j0 + tg];
                a[mi][1] = Ss[(i + grp + 8) * PS + j0 + tg];
                a[mi][2] = Ss[(i + grp) * PS + j0 + tg + 4];
                a[mi][3] = Ss[(i + grp + 8) * PS + j0 + tg + 4];
            }
#pragma unroll
            for (int ni = 0; ni < 4; ++ni) {
                const int e = wn + (ni << 3) + grp;
                bb[ni][0] = Vs[(j0 + tg) * PV + e];
                bb[ni][1] = Vs[(j0 + tg + 4) * PV + e];
            }
#pragma unroll
            for (int mi = 0; mi < 2; ++mi)
#pragma unroll
                for (int ni = 0; ni < 4; ++ni) mma_tf32(acc[mi][ni], a[mi], bb[ni]);
        }

        // 2b: sum over d (64), P = KV_prev
#pragma unroll
        for (int d0 = 0; d0 < KD; d0 += 8) {
            unsigned a[2][4], bb[4][2];
#pragma unroll
            for (int mi = 0; mi < 2; ++mi) {
                const int i = wm + (mi << 4);
                a[mi][0] = Qs[(i + grp) * PQ + d0 + tg];
                a[mi][1] = Qs[(i + grp + 8) * PQ + d0 + tg];
                a[mi][2] = Qs[(i + grp) * PQ + d0 + tg + 4];
                a[mi][3] = Qs[(i + grp + 8) * PQ + d0 + tg + 4];
            }
#pragma unroll
            for (int ni = 0; ni < 4; ++ni) {
                const int e = wn + (ni << 3) + grp;
                bb[ni][0] = Ps[(d0 + tg) * PV + e];
                bb[ni][1] = Ps[(d0 + tg + 4) * PV + e];
            }
#pragma unroll
            for (int mi = 0; mi < 2; ++mi)
#pragma unroll
                for (int ni = 0; ni < 4; ++ni) mma_tf32(acc[mi][ni], a[mi], bb[ni]);
        }

        // Store O.
#pragma unroll
        for (int mi = 0; mi < 2; ++mi)
#pragma unroll
            for (int ni = 0; ni < 4; ++ni) {
                const int i = wm + (mi << 4) + grp;
                const int e = wn + (ni << 3) + (tg << 1);
                *(float2*)&O[base + i * KROW + e] =
                    make_float2(acc[mi][ni][0], acc[mi][ni][1]);
                *(float2*)&O[base + (i + 8) * KROW + e] =
                    make_float2(acc[mi][ni][2], acc[mi][ni][3]);
            }
    }
}

// ---------------------------------------------------------------------------
// Launch
// ---------------------------------------------------------------------------
static const int kKvSmem = (KD * PKT + KC * PV) * (int)sizeof(unsigned);      // 70656
static const int kOutSmem =
    (2 * KC * PQ + KC * PV + KD * PV + KC * PS) * (int)sizeof(unsigned);      // 192512

extern "C" void kernel_launch(void* const* d_in, const int* in_sizes, int n_in,
                              void* d_out, int out_size) {
    const float* q = (const float*)d_in[0];
    const float* k = (const float*)d_in[1];
    const float* v = (const float*)d_in[2];
    float* out = (float*)d_out;

    cudaFuncSetAttribute(kv_kernel, cudaFuncAttributeMaxDynamicSharedMemorySize,
                         kKvSmem);
    cudaFuncSetAttribute(out_kernel, cudaFuncAttributeMaxDynamicSharedMemorySize,
                         kOutSmem);

    kv_kernel<<<KCHUNKS, 128, kKvSmem>>>(k, v);
    scan_kernel<<<KBH * 16, 256>>>();
    out_kernel<<<KCHUNKS, 256, kOutSmem>>>(q, k, v, out);
}